// round 15
// baseline (speedup 1.0000x reference)
#include <cuda_runtime.h>
#include <cuda_bf16.h>
#include <math.h>
#include <cstdint>

#define BB 64
#define NN 256
#define HH 8
#define FF 256
#define D_GAT 2048
#define D_LBL 512
#define D_VIS 2048
#define D_EMB 512
#define ALPHA 0.2f
#define CMAX 64

// ---------------- scratch (device globals; no allocations allowed) ----------
__device__ float g_L[NN * D_GAT];                       // labels @ W_lbl (2 MiB)
__device__ float g_V[BB * D_GAT];                       // visual @ W_vis (summed)
__device__ float g_Vpart[4 * BB * D_GAT];               // V split-K partials
__device__ float g_fcpart[4 * BB * D_EMB];
__device__ float g_Ls[NN * HH];
__device__ float g_Ld[NN * HH];
__device__ float g_Vs[BB * HH];
__device__ float g_Vd[BB * HH];
__device__ int   g_jidx[NN * CMAX];                     // CSR cols (shared mask)
__device__ int   g_cnt[NN];
__device__ __nv_bfloat16 g_out_bf[(size_t)BB * NN * D_GAT];  // 64 MiB (post-ELU)
__device__ float g_logits[BB * NN];                     // pooling logits
__device__ float g_pooled[BB * D_GAT];

// ---------------- helpers ---------------------------------------------------
__device__ __forceinline__ float warp_sum(float v) {
    #pragma unroll
    for (int o = 16; o; o >>= 1) v += __shfl_xor_sync(0xffffffffu, v, o);
    return v;
}
__device__ __forceinline__ float warp_max(float v) {
    #pragma unroll
    for (int o = 16; o; o >>= 1) v = fmaxf(v, __shfl_xor_sync(0xffffffffu, v, o));
    return v;
}
// packed f32x2 FMA (SASS FFMA2) — only reachable via PTX
__device__ __forceinline__ void ffma2(unsigned long long& acc,
                                      unsigned long long a,
                                      unsigned long long b) {
    asm("fma.rn.f32x2 %0, %1, %2, %0;" : "+l"(acc) : "l"(a), "l"(b));
}
__device__ __forceinline__ unsigned long long pack2(float x) {
    unsigned long long r;
    asm("mov.b64 %0, {%1, %1};" : "=l"(r) : "r"(__float_as_uint(x)));
    return r;
}
__device__ __forceinline__ void unpack2(unsigned long long p, float& lo, float& hi) {
    unsigned int a, b;
    asm("mov.b64 {%0, %1}, %2;" : "=r"(a), "=r"(b) : "l"(p));
    lo = __uint_as_float(a); hi = __uint_as_float(b);
}

// ---------------- fused projection GEMM (FFMA2): L (4 tiles) + V (4 parts) --
__global__ void gemm_LV_kernel(const float* __restrict__ labels,
                               const float* __restrict__ visual,
                               const float* __restrict__ W)
{
    __shared__ float As[16][64];
    __shared__ float Bs[16][64];
    const int tid = threadIdx.x;
    const int tx = tid & 15, ty = tid >> 4;
    const int colBase = blockIdx.x * 64;
    const int y = blockIdx.y;

    const float* A; const float* Bm; float* C;
    int lda, rowBase, kBase;
    if (y < 4) {                 // L = labels @ W[:512]
        A = labels; lda = D_LBL; rowBase = y * 64; kBase = 0;
        Bm = W; C = g_L;
    } else {                     // V part p = y-4
        A = visual; lda = D_VIS; rowBase = 0; kBase = (y - 4) * 512;
        Bm = W + (size_t)D_LBL * D_GAT; C = g_Vpart + (size_t)(y - 4) * BB * D_GAT;
    }

    const int am = tid >> 2;
    const int ak = (tid & 3) * 4;
    const int bk = tid >> 4;
    const int bn = (tid & 15) * 4;
    unsigned long long acc2[4][2];
    #pragma unroll
    for (int i = 0; i < 4; i++) { acc2[i][0] = 0ULL; acc2[i][1] = 0ULL; }

    for (int k0 = kBase; k0 < kBase + 512; k0 += 16) {
        float4 av = *(const float4*)&A[(size_t)(rowBase + am) * lda + k0 + ak];
        As[ak + 0][am] = av.x; As[ak + 1][am] = av.y;
        As[ak + 2][am] = av.z; As[ak + 3][am] = av.w;
        *(float4*)&Bs[bk][bn] =
            *(const float4*)&Bm[(size_t)(k0 + bk) * D_GAT + colBase + bn];
        __syncthreads();
        #pragma unroll
        for (int kk = 0; kk < 16; kk++) {
            const unsigned long long* bp =
                (const unsigned long long*)&Bs[kk][tx * 4];
            unsigned long long b01 = bp[0], b23 = bp[1];
            #pragma unroll
            for (int i = 0; i < 4; i++) {
                unsigned long long a2 = pack2(As[kk][ty * 4 + i]);
                ffma2(acc2[i][0], a2, b01);
                ffma2(acc2[i][1], a2, b23);
            }
        }
        __syncthreads();
    }
    #pragma unroll
    for (int i = 0; i < 4; i++) {
        int r = rowBase + ty * 4 + i;
        float v0, v1, v2, v3;
        unpack2(acc2[i][0], v0, v1);
        unpack2(acc2[i][1], v2, v3);
        float* cp = &C[(size_t)r * D_GAT + colBase + tx * 4];
        cp[0] = v0; cp[1] = v1; cp[2] = v2; cp[3] = v3;
    }
}

// ---------------- generic split-K GEMM (final fc) ---------------------------
__global__ void gemm_f32_splitk(const float* __restrict__ A, int lda,
                                const float* __restrict__ Bm, int ldb,
                                float* __restrict__ Cpart, int ldc,
                                int kChunk, size_t partStride)
{
    __shared__ float As[16][64];
    __shared__ float Bs[16][64];
    const int tid = threadIdx.x;
    const int tx = tid & 15, ty = tid >> 4;
    const int colBase = blockIdx.x * 64;
    const int rowBase = blockIdx.y * 64;
    const int kBase = blockIdx.z * kChunk;
    const int am = tid >> 2;
    const int ak = (tid & 3) * 4;
    const int bk = tid >> 4;
    const int bn = (tid & 15) * 4;
    float acc[4][4] = {};
    for (int k0 = kBase; k0 < kBase + kChunk; k0 += 16) {
        float4 av = *(const float4*)&A[(size_t)(rowBase + am) * lda + k0 + ak];
        As[ak + 0][am] = av.x; As[ak + 1][am] = av.y;
        As[ak + 2][am] = av.z; As[ak + 3][am] = av.w;
        *(float4*)&Bs[bk][bn] =
            *(const float4*)&Bm[(size_t)(k0 + bk) * ldb + colBase + bn];
        __syncthreads();
        #pragma unroll
        for (int kk = 0; kk < 16; kk++) {
            float ra[4], rb[4];
            #pragma unroll
            for (int i = 0; i < 4; i++) ra[i] = As[kk][ty * 4 + i];
            #pragma unroll
            for (int j = 0; j < 4; j++) rb[j] = Bs[kk][tx * 4 + j];
            #pragma unroll
            for (int i = 0; i < 4; i++)
                #pragma unroll
                for (int j = 0; j < 4; j++)
                    acc[i][j] += ra[i] * rb[j];
        }
        __syncthreads();
    }
    float* C = Cpart + blockIdx.z * partStride;
    #pragma unroll
    for (int i = 0; i < 4; i++) {
        int r = rowBase + ty * 4 + i;
        #pragma unroll
        for (int j = 0; j < 4; j++)
            C[(size_t)r * ldc + colBase + tx * 4 + j] = acc[i][j];
    }
}

__global__ void reduce_parts(const float* __restrict__ part,
                             float* __restrict__ outp,
                             int nparts, size_t stride, int total,
                             const float* __restrict__ bias, int mask)
{
    int i = blockIdx.x * 256 + threadIdx.x;
    if (i >= total) return;
    float s = 0.f;
    for (int p = 0; p < nparts; p++) s += part[p * stride + i];
    if (bias) s += bias[i & mask];
    outp[i] = s;
}

// ---------------- attention scalars + V reduction ---------------------------
__global__ void dots_kernel(const float* __restrict__ a_src,
                            const float* __restrict__ a_dst)
{
    __shared__ float ss[8], sd[8];
    int idx = blockIdx.x, t = threadIdx.x;
    float v; float *outS, *outD; int h;
    if (idx < NN * HH) {
        int n = idx >> 3; h = idx & 7;
        v = g_L[(size_t)n * D_GAT + h * FF + t];
        outS = &g_Ls[idx]; outD = &g_Ld[idx];
    } else {
        int k = idx - NN * HH;
        int b = k >> 3; h = k & 7;
        int off = b * D_GAT + h * FF + t;
        v = g_Vpart[off] + g_Vpart[BB * D_GAT + off]
          + g_Vpart[2 * BB * D_GAT + off] + g_Vpart[3 * BB * D_GAT + off];
        g_V[off] = v;
        outS = &g_Vs[k]; outD = &g_Vd[k];
    }
    float s = warp_sum(v * a_src[h * FF + t]);
    float d = warp_sum(v * a_dst[h * FF + t]);
    int w = t >> 5, l = t & 31;
    if (l == 0) { ss[w] = s; sd[w] = d; }
    __syncthreads();
    if (t == 0) {
        float S = 0.f, D = 0.f;
        #pragma unroll
        for (int i = 0; i < 8; i++) { S += ss[i]; D += sd[i]; }
        *outS = S; *outD = D;
    }
}

// ---------------- shared CSR build (mask is batch/head independent) ---------
__global__ void csr_kernel(const float* __restrict__ adj)
{
    int lane = threadIdx.x & 31;
    int i = blockIdx.x * 8 + (threadIdx.x >> 5);
    float4 a0 = *(const float4*)&adj[i * NN + lane * 8];
    float4 a1 = *(const float4*)&adj[i * NN + lane * 8 + 4];
    float am[8] = {a0.x, a0.y, a0.z, a0.w, a1.x, a1.y, a1.z, a1.w};
    int cl = 0;
    #pragma unroll
    for (int k = 0; k < 8; k++) cl += (am[k] > 0.f) ? 1 : 0;
    int incl = cl;
    #pragma unroll
    for (int o = 1; o < 32; o <<= 1) {
        int n = __shfl_up_sync(0xffffffffu, incl, o);
        if (lane >= o) incl += n;
    }
    int run = incl - cl;
    #pragma unroll
    for (int k = 0; k < 8; k++) {
        if (am[k] > 0.f) {
            if (run < CMAX) g_jidx[i * CMAX + run] = lane * 8 + k;
            run++;
        }
    }
    if (lane == 31) g_cnt[i] = min(incl, CMAX);
}

// ---------------- fused sparse softmax + SpMM + ELU (FFMA2, 2f x 16b) -------
// block = (i, h, bhalf 32); 256 threads; thread = f-pair x 16 b; 4 CTAs/SM.
__global__ void __launch_bounds__(256, 4) spmm_kernel()
{
    __shared__ float sLdc[CMAX];
    __shared__ int   sj[CMAX];            // byte offsets into g_L rows
    __shared__ float w_s[CMAX * 32];      // [c][32 b] 8 KB
    __shared__ float sc0[32], sm_[32], sinv[32];
    __shared__ float smx;
    const int tid = threadIdx.x;
    const int blk = blockIdx.x;           // (ih<<1) | half
    const int half = blk & 1;
    const int ih = blk >> 1;
    const int i = ih >> 3;
    const int h = ih & 7;
    const int bB = half * 32;             // block b base
    const int tg = tid >> 7;              // 0/1 -> 16-b subgroup
    const int fi = tid & 127;
    const int b0 = bB + tg * 16;          // thread b base
    const int hf = h * FF + fi * 2;       // f-pair base
    const int cnt = g_cnt[i];
    const int cntP = (cnt + 3) & ~3;

    if (tid < CMAX) {
        int j = (tid < cnt) ? g_jidx[i * CMAX + tid] : 0;
        sj[tid] = j * (int)(D_GAT * sizeof(float));
        sLdc[tid] = (tid < cnt) ? g_Ld[j * HH + h] : -3.4e38f;
    }
    __syncthreads();
    if (tid < 32) {                       // b-independent max over c (warp 0)
        float mx = fmaxf(sLdc[tid], sLdc[tid + 32]);
        mx = warp_max(mx);
        if (tid == 0) smx = mx;
    }
    __syncthreads();
    if (tid < 32) {
        int b = bB + tid;
        float c0 = g_Ls[i * HH + h] + g_Vs[b * HH + h] + g_Vd[b * HH + h];
        float m = c0 + smx;               // LeakyReLU monotone
        sc0[tid] = c0;
        sm_[tid] = m > 0.f ? m : ALPHA * m;
    }
    __syncthreads();
    for (int idx = tid; idx < cntP * 32; idx += 256) {
        int c = idx >> 5, bl = idx & 31;
        float w = 0.f;
        if (c < cnt) {
            float e = sc0[bl] + sLdc[c];
            e = e > 0.f ? e : ALPHA * e;
            w = __expf(e - sm_[bl]);
        }
        w_s[idx] = w;
    }
    __syncthreads();
    if (tid < 32) {
        float s = 0.f;
        for (int c = 0; c < cnt; c++) s += w_s[c * 32 + tid];
        sinv[tid] = 1.f / s;
    }
    __syncthreads();

    // acc2[ff][p]: f = hf+ff, b pair (b0+2p, b0+2p+1)
    unsigned long long acc2[2][8];
    #pragma unroll
    for (int p = 0; p < 8; p++) { acc2[0][p] = 0ULL; acc2[1][p] = 0ULL; }

    const char* Lb = (const char*)g_L + (size_t)hf * sizeof(float);
    for (int c0i = 0; c0i < cntP; c0i += 4) {
        float2 Lr[4];
        #pragma unroll
        for (int t = 0; t < 4; t++)
            Lr[t] = *(const float2*)(Lb + sj[c0i + t]);
        #pragma unroll
        for (int t = 0; t < 4; t++) {
            const ulonglong2* wp =
                (const ulonglong2*)&w_s[(c0i + t) * 32 + tg * 16];
            ulonglong2 w01 = wp[0];       // b-pairs (0,1),(2,3)
            ulonglong2 w23 = wp[1];       // (4,5),(6,7)
            ulonglong2 w45 = wp[2];       // (8,9),(10,11)
            ulonglong2 w67 = wp[3];       // (12,13),(14,15)
            unsigned long long L0 = pack2(Lr[t].x);
            unsigned long long L1 = pack2(Lr[t].y);
            ffma2(acc2[0][0], w01.x, L0); ffma2(acc2[1][0], w01.x, L1);
            ffma2(acc2[0][1], w01.y, L0); ffma2(acc2[1][1], w01.y, L1);
            ffma2(acc2[0][2], w23.x, L0); ffma2(acc2[1][2], w23.x, L1);
            ffma2(acc2[0][3], w23.y, L0); ffma2(acc2[1][3], w23.y, L1);
            ffma2(acc2[0][4], w45.x, L0); ffma2(acc2[1][4], w45.x, L1);
            ffma2(acc2[0][5], w45.y, L0); ffma2(acc2[1][5], w45.y, L1);
            ffma2(acc2[0][6], w67.x, L0); ffma2(acc2[1][6], w67.x, L1);
            ffma2(acc2[0][7], w67.y, L0); ffma2(acc2[1][7], w67.y, L1);
        }
    }

    // epilogue: normalize, +V, fast ELU, bf16x2 stores — pointer strides
    const char* vp = (const char*)&g_V[b0 * D_GAT + hf];
    char* op = (char*)&g_out_bf[((size_t)(b0 * NN + i)) * D_GAT + hf];
    const size_t vstride = (size_t)D_GAT * sizeof(float);
    const size_t ostride = (size_t)NN * D_GAT * sizeof(__nv_bfloat16);
    const int sb = tg * 16;
    #pragma unroll
    for (int p = 0; p < 8; p++) {
        float f0a, f0b, f1a, f1b;
        unpack2(acc2[0][p], f0a, f0b);    // f0 at (b2p, b2p+1)
        unpack2(acc2[1][p], f1a, f1b);    // f1 at (b2p, b2p+1)
        float2 vA = *(const float2*)vp;
        float2 vBv = *(const float2*)(vp + vstride);
        float iA = sinv[sb + 2 * p], iB = sinv[sb + 2 * p + 1];
        float o00 = f0a * iA + vA.x;      // (bA, f0)
        float o01 = f1a * iA + vA.y;      // (bA, f1)
        float o10 = f0b * iB + vBv.x;     // (bB, f0)
        float o11 = f1b * iB + vBv.y;     // (bB, f1)
        o00 = o00 > 0.f ? o00 : (__expf(o00) - 1.f);
        o01 = o01 > 0.f ? o01 : (__expf(o01) - 1.f);
        o10 = o10 > 0.f ? o10 : (__expf(o10) - 1.f);
        o11 = o11 > 0.f ? o11 : (__expf(o11) - 1.f);
        *(__nv_bfloat162*)op = __floats2bfloat162_rn(o00, o01);
        *(__nv_bfloat162*)(op + ostride) = __floats2bfloat162_rn(o10, o11);
        vp += 2 * vstride;
        op += 2 * ostride;
    }
}

// ---------------- pooling logits: logits[b][n] = out_bf[b,n,:] . pool_q -----
__global__ void logits_kernel(const float* __restrict__ pool_q)
{
    __shared__ float sq[D_GAT];
    const int tid = threadIdx.x;
    const int wid = tid >> 5, lane = tid & 31;
    #pragma unroll
    for (int k = 0; k < 8; k++) sq[tid + k * 256] = pool_q[tid + k * 256];
    __syncthreads();

    const int b = blockIdx.x >> 5;
    const int n = (blockIdx.x & 31) * 8 + wid;
    const uint2* row = (const uint2*)&g_out_bf[((size_t)(b * NN + n)) * D_GAT];
    float s = 0.f;
    #pragma unroll
    for (int k = 0; k < 16; k++) {
        int idx = lane + k * 32;
        uint2 v = row[idx];
        const __nv_bfloat162* p0 = (const __nv_bfloat162*)&v.x;
        const __nv_bfloat162* p1 = (const __nv_bfloat162*)&v.y;
        float2 f0 = __bfloat1622float2(*p0);
        float2 f1 = __bfloat1622float2(*p1);
        const float* qp = &sq[idx * 4];
        s += f0.x * qp[0] + f0.y * qp[1] + f1.x * qp[2] + f1.y * qp[3];
    }
    s = warp_sum(s);
    if (lane == 0) g_logits[b * NN + n] = s;
}

// ---------------- fused pooling softmax + pooled ----------------------------
__global__ void pooled_pw_kernel()
{
    __shared__ float pw_s[NN];
    __shared__ float sh[8];
    __shared__ float bc;
    const int b = blockIdx.y;
    const int t = threadIdx.x;

    float x = g_logits[b * NN + t];
    float m = warp_max(x);
    if ((t & 31) == 0) sh[t >> 5] = m;
    __syncthreads();
    if (t < 8) {
        float v = sh[t];
        #pragma unroll
        for (int o = 4; o; o >>= 1) v = fmaxf(v, __shfl_xor_sync(0xffu, v, o));
        if (t == 0) bc = v;
    }
    __syncthreads();
    float M = bc;
    float e = __expf(x - M);
    float s = warp_sum(e);
    if ((t & 31) == 0) sh[t >> 5] = s;
    __syncthreads();
    if (t < 8) {
        float v = sh[t];
        #pragma unroll
        for (int o = 4; o; o >>= 1) v += __shfl_xor_sync(0xffu, v, o);
        if (t == 0) bc = v;
    }
    __syncthreads();
    pw_s[t] = e / bc;
    __syncthreads();

    const int d = blockIdx.x * 256 + t;
    const __nv_bfloat16* base = &g_out_bf[(size_t)b * NN * D_GAT + d];
    float acc = 0.f;
    #pragma unroll 4
    for (int n = 0; n < NN; n++)
        acc += pw_s[n] * __bfloat162float(base[(size_t)n * D_GAT]);
    g_pooled[b * D_GAT + d] = acc;
}

// ---------------- launch ----------------------------------------------------
extern "C" void kernel_launch(void* const* d_in, const int* in_sizes, int n_in,
                              void* d_out, int out_size)
{
    const float* visual = (const float*)d_in[0];   // (64, 2048)
    const float* labels = (const float*)d_in[1];   // (256, 512)
    const float* adj    = (const float*)d_in[2];   // (256, 256)
    const float* W      = (const float*)d_in[3];   // (2560, 8, 256)
    const float* a_src  = (const float*)d_in[4];
    const float* a_dst  = (const float*)d_in[5];
    const float* pool_q = (const float*)d_in[6];
    const float* fcW    = (const float*)d_in[7];   // (2048, 512)
    const float* fcb    = (const float*)d_in[8];
    float* out = (float*)d_out;                    // (64, 512)

    float *pFcpart, *pPooled;
    cudaGetSymbolAddress((void**)&pFcpart, g_fcpart);
    cudaGetSymbolAddress((void**)&pPooled, g_pooled);

    // 1: L + V projections (V as 4 K-parts), FFMA2 inner loop
    gemm_LV_kernel<<<dim3(D_GAT / 64, 8), 256>>>(labels, visual, W);
    // 2: attention scalars + V reduction
    dots_kernel<<<NN * HH + BB * HH, 256>>>(a_src, a_dst);
    // 3: shared CSR build
    csr_kernel<<<NN / 8, 256>>>(adj);
    // 4: fused softmax + SpMM(FFMA2, 2f x 16b) + ELU      [profiled slot]
    spmm_kernel<<<NN * HH * 2, 256>>>();
    // 5: pooling logits (DRAM pass over g_out_bf)
    logits_kernel<<<BB * NN / 8, 256>>>(pool_q);
    // 6: pooling softmax + pooled
    pooled_pw_kernel<<<dim3(D_GAT / 256, BB), 256>>>();
    // 7-8: final fc
    gemm_f32_splitk<<<dim3(D_EMB / 64, 1, 4), 256>>>(
        pPooled, D_GAT, fcW, D_EMB, pFcpart, D_EMB, 512, (size_t)BB * D_EMB);
    reduce_parts<<<(BB * D_EMB) / 256, 256>>>(
        pFcpart, out, 4, (size_t)BB * D_EMB, BB * D_EMB, fcb, D_EMB - 1);
}

// round 16
// speedup vs baseline: 1.1923x; 1.1923x over previous
#include <cuda_runtime.h>
#include <cuda_bf16.h>
#include <math.h>
#include <cstdint>

#define BB 64
#define NN 256
#define HH 8
#define FF 256
#define D_GAT 2048
#define D_LBL 512
#define D_VIS 2048
#define D_EMB 512
#define ALPHA 0.2f
#define CMAX 64

// ---------------- scratch (device globals; no allocations allowed) ----------
__device__ float g_L[NN * D_GAT];                       // labels @ W_lbl (2 MiB)
__device__ float g_V[BB * D_GAT];                       // visual @ W_vis (summed)
__device__ float g_Vpart[4 * BB * D_GAT];               // V split-K partials
__device__ float g_fcpart[8 * BB * D_EMB];
__device__ float g_Ls[NN * HH];
__device__ float g_Ld[NN * HH];
__device__ float g_Vs[BB * HH];
__device__ float g_Vd[BB * HH];
__device__ int   g_jidx[NN * CMAX];                     // CSR cols (shared mask)
__device__ int   g_cnt[NN];
__device__ __nv_bfloat16 g_out_bf[(size_t)BB * NN * D_GAT];  // 64 MiB (post-ELU)
__device__ float g_logits[BB * NN];                     // pooling logits
__device__ float g_pooled[BB * D_GAT];

// ---------------- helpers ---------------------------------------------------
__device__ __forceinline__ float warp_sum(float v) {
    #pragma unroll
    for (int o = 16; o; o >>= 1) v += __shfl_xor_sync(0xffffffffu, v, o);
    return v;
}
__device__ __forceinline__ float warp_max(float v) {
    #pragma unroll
    for (int o = 16; o; o >>= 1) v = fmaxf(v, __shfl_xor_sync(0xffffffffu, v, o));
    return v;
}
// packed f32x2 FMA (SASS FFMA2) — only reachable via PTX
__device__ __forceinline__ void ffma2(unsigned long long& acc,
                                      unsigned long long a,
                                      unsigned long long b) {
    asm("fma.rn.f32x2 %0, %1, %2, %0;" : "+l"(acc) : "l"(a), "l"(b));
}
__device__ __forceinline__ unsigned long long pack2(float x) {
    unsigned long long r;
    asm("mov.b64 %0, {%1, %1};" : "=l"(r) : "r"(__float_as_uint(x)));
    return r;
}
__device__ __forceinline__ void unpack2(unsigned long long p, float& lo, float& hi) {
    unsigned int a, b;
    asm("mov.b64 {%0, %1}, %2;" : "=r"(a), "=r"(b) : "l"(p));
    lo = __uint_as_float(a); hi = __uint_as_float(b);
}

// ---------------- fused projection GEMM (FFMA2): L (4 tiles) + V (4 parts) --
__global__ void gemm_LV_kernel(const float* __restrict__ labels,
                               const float* __restrict__ visual,
                               const float* __restrict__ W)
{
    __shared__ float As[16][64];
    __shared__ float Bs[16][64];
    const int tid = threadIdx.x;
    const int tx = tid & 15, ty = tid >> 4;
    const int colBase = blockIdx.x * 64;
    const int y = blockIdx.y;

    const float* A; const float* Bm; float* C;
    int lda, rowBase, kBase;
    if (y < 4) {                 // L = labels @ W[:512]
        A = labels; lda = D_LBL; rowBase = y * 64; kBase = 0;
        Bm = W; C = g_L;
    } else {                     // V part p = y-4
        A = visual; lda = D_VIS; rowBase = 0; kBase = (y - 4) * 512;
        Bm = W + (size_t)D_LBL * D_GAT; C = g_Vpart + (size_t)(y - 4) * BB * D_GAT;
    }

    const int am = tid >> 2;
    const int ak = (tid & 3) * 4;
    const int bk = tid >> 4;
    const int bn = (tid & 15) * 4;
    unsigned long long acc2[4][2];
    #pragma unroll
    for (int i = 0; i < 4; i++) { acc2[i][0] = 0ULL; acc2[i][1] = 0ULL; }

    for (int k0 = kBase; k0 < kBase + 512; k0 += 16) {
        float4 av = *(const float4*)&A[(size_t)(rowBase + am) * lda + k0 + ak];
        As[ak + 0][am] = av.x; As[ak + 1][am] = av.y;
        As[ak + 2][am] = av.z; As[ak + 3][am] = av.w;
        *(float4*)&Bs[bk][bn] =
            *(const float4*)&Bm[(size_t)(k0 + bk) * D_GAT + colBase + bn];
        __syncthreads();
        #pragma unroll
        for (int kk = 0; kk < 16; kk++) {
            const unsigned long long* bp =
                (const unsigned long long*)&Bs[kk][tx * 4];
            unsigned long long b01 = bp[0], b23 = bp[1];
            #pragma unroll
            for (int i = 0; i < 4; i++) {
                unsigned long long a2 = pack2(As[kk][ty * 4 + i]);
                ffma2(acc2[i][0], a2, b01);
                ffma2(acc2[i][1], a2, b23);
            }
        }
        __syncthreads();
    }
    #pragma unroll
    for (int i = 0; i < 4; i++) {
        int r = rowBase + ty * 4 + i;
        float v0, v1, v2, v3;
        unpack2(acc2[i][0], v0, v1);
        unpack2(acc2[i][1], v2, v3);
        float* cp = &C[(size_t)r * D_GAT + colBase + tx * 4];
        cp[0] = v0; cp[1] = v1; cp[2] = v2; cp[3] = v3;
    }
}

// ---------------- generic split-K GEMM (final fc) ---------------------------
__global__ void gemm_f32_splitk(const float* __restrict__ A, int lda,
                                const float* __restrict__ Bm, int ldb,
                                float* __restrict__ Cpart, int ldc,
                                int kChunk, size_t partStride)
{
    __shared__ float As[16][64];
    __shared__ float Bs[16][64];
    const int tid = threadIdx.x;
    const int tx = tid & 15, ty = tid >> 4;
    const int colBase = blockIdx.x * 64;
    const int rowBase = blockIdx.y * 64;
    const int kBase = blockIdx.z * kChunk;
    const int am = tid >> 2;
    const int ak = (tid & 3) * 4;
    const int bk = tid >> 4;
    const int bn = (tid & 15) * 4;
    float acc[4][4] = {};
    for (int k0 = kBase; k0 < kBase + kChunk; k0 += 16) {
        float4 av = *(const float4*)&A[(size_t)(rowBase + am) * lda + k0 + ak];
        As[ak + 0][am] = av.x; As[ak + 1][am] = av.y;
        As[ak + 2][am] = av.z; As[ak + 3][am] = av.w;
        *(float4*)&Bs[bk][bn] =
            *(const float4*)&Bm[(size_t)(k0 + bk) * ldb + colBase + bn];
        __syncthreads();
        #pragma unroll
        for (int kk = 0; kk < 16; kk++) {
            float ra[4], rb[4];
            #pragma unroll
            for (int i = 0; i < 4; i++) ra[i] = As[kk][ty * 4 + i];
            #pragma unroll
            for (int j = 0; j < 4; j++) rb[j] = Bs[kk][tx * 4 + j];
            #pragma unroll
            for (int i = 0; i < 4; i++)
                #pragma unroll
                for (int j = 0; j < 4; j++)
                    acc[i][j] += ra[i] * rb[j];
        }
        __syncthreads();
    }
    float* C = Cpart + blockIdx.z * partStride;
    #pragma unroll
    for (int i = 0; i < 4; i++) {
        int r = rowBase + ty * 4 + i;
        #pragma unroll
        for (int j = 0; j < 4; j++)
            C[(size_t)r * ldc + colBase + tx * 4 + j] = acc[i][j];
    }
}

__global__ void reduce_parts(const float* __restrict__ part,
                             float* __restrict__ outp,
                             int nparts, size_t stride, int total,
                             const float* __restrict__ bias, int mask)
{
    int i = blockIdx.x * 256 + threadIdx.x;
    if (i >= total) return;
    float s = 0.f;
    for (int p = 0; p < nparts; p++) s += part[p * stride + i];
    if (bias) s += bias[i & mask];
    outp[i] = s;
}

// ---------------- attention scalars + V reduction + CSR build ---------------
// blocks [0, N*H): Ls/Ld ; [N*H, N*H+B*H): Vs/Vd (+V sum) ; last 32: CSR
__global__ void dots_kernel(const float* __restrict__ a_src,
                            const float* __restrict__ a_dst,
                            const float* __restrict__ adj)
{
    __shared__ float ss[8], sd[8];
    int idx = blockIdx.x, t = threadIdx.x;

    if (idx >= NN * HH + BB * HH) {
        // ---- CSR build: 8 warps per block, warp -> row i ----
        int lane = t & 31;
        int i = (idx - NN * HH - BB * HH) * 8 + (t >> 5);
        float4 a0 = *(const float4*)&adj[i * NN + lane * 8];
        float4 a1 = *(const float4*)&adj[i * NN + lane * 8 + 4];
        float am[8] = {a0.x, a0.y, a0.z, a0.w, a1.x, a1.y, a1.z, a1.w};
        int cl = 0;
        #pragma unroll
        for (int k = 0; k < 8; k++) cl += (am[k] > 0.f) ? 1 : 0;
        int incl = cl;
        #pragma unroll
        for (int o = 1; o < 32; o <<= 1) {
            int n = __shfl_up_sync(0xffffffffu, incl, o);
            if (lane >= o) incl += n;
        }
        int run = incl - cl;
        #pragma unroll
        for (int k = 0; k < 8; k++) {
            if (am[k] > 0.f) {
                if (run < CMAX) g_jidx[i * CMAX + run] = lane * 8 + k;
                run++;
            }
        }
        if (lane == 31) g_cnt[i] = min(incl, CMAX);
        return;
    }

    float v; float *outS, *outD; int h;
    if (idx < NN * HH) {
        int n = idx >> 3; h = idx & 7;
        v = g_L[(size_t)n * D_GAT + h * FF + t];
        outS = &g_Ls[idx]; outD = &g_Ld[idx];
    } else {
        int k = idx - NN * HH;
        int b = k >> 3; h = k & 7;
        int off = b * D_GAT + h * FF + t;
        v = g_Vpart[off] + g_Vpart[BB * D_GAT + off]
          + g_Vpart[2 * BB * D_GAT + off] + g_Vpart[3 * BB * D_GAT + off];
        g_V[off] = v;
        outS = &g_Vs[k]; outD = &g_Vd[k];
    }
    float s = warp_sum(v * a_src[h * FF + t]);
    float d = warp_sum(v * a_dst[h * FF + t]);
    int w = t >> 5, l = t & 31;
    if (l == 0) { ss[w] = s; sd[w] = d; }
    __syncthreads();
    if (t == 0) {
        float S = 0.f, D = 0.f;
        #pragma unroll
        for (int i = 0; i < 8; i++) { S += ss[i]; D += sd[i]; }
        *outS = S; *outD = D;
    }
}

// ---------------- fused sparse softmax + SpMM + ELU (FFMA2) -----------------
// block = (i, h, bquarter); 256 threads = f; acc = 8 x f32x2 (16 b); 6 CTAs/SM.
__global__ void __launch_bounds__(256, 6) spmm_kernel()
{
    __shared__ float sLdc[CMAX];
    __shared__ int   sj[CMAX];            // byte offsets into g_L rows
    __shared__ float w_s[CMAX * 16];      // [c][16 b] 4 KB
    __shared__ float sc0[16], sm[16];
    __shared__ float sinv[16];
    __shared__ float smx;
    const int tid = threadIdx.x;
    const int blk = blockIdx.x;           // (ih<<2) | quarter
    const int q = blk & 3;
    const int ih = blk >> 2;
    const int i = ih >> 3;
    const int h = ih & 7;
    const int b0 = q * 16;
    const int hf = h * FF + tid;
    const int cnt = g_cnt[i];
    const int cntP = (cnt + 3) & ~3;

    if (tid < CMAX) {
        int j = (tid < cnt) ? g_jidx[i * CMAX + tid] : 0;
        sj[tid] = j * (int)(D_GAT * sizeof(float));
        sLdc[tid] = (tid < cnt) ? g_Ld[j * HH + h] : -3.4e38f;
    }
    __syncthreads();
    if (tid < 32) {                       // b-independent max over c (warp 0)
        float mx = fmaxf(sLdc[tid], sLdc[tid + 32]);
        mx = warp_max(mx);
        if (tid == 0) smx = mx;
    }
    __syncthreads();
    if (tid < 16) {
        int b = b0 + tid;
        float c0 = g_Ls[i * HH + h] + g_Vs[b * HH + h] + g_Vd[b * HH + h];
        float m = c0 + smx;               // LeakyReLU monotone
        sc0[tid] = c0;
        sm[tid] = m > 0.f ? m : ALPHA * m;
    }
    __syncthreads();
    for (int idx = tid; idx < cntP * 16; idx += 256) {
        int c = idx >> 4, bl = idx & 15;
        float w = 0.f;
        if (c < cnt) {
            float e = sc0[bl] + sLdc[c];
            e = e > 0.f ? e : ALPHA * e;
            w = __expf(e - sm[bl]);
        }
        w_s[idx] = w;
    }
    __syncthreads();
    if (tid < 16) {
        float s = 0.f;
        for (int c = 0; c < cnt; c++) s += w_s[c * 16 + tid];
        sinv[tid] = 1.f / s;
    }
    __syncthreads();

    unsigned long long acc2[8];
    #pragma unroll
    for (int p = 0; p < 8; p++) acc2[p] = 0ULL;

    const char* Lb = (const char*)g_L + (size_t)hf * sizeof(float);
    for (int c0i = 0; c0i < cntP; c0i += 4) {
        float Lr[4];
        #pragma unroll
        for (int t = 0; t < 4; t++)
            Lr[t] = *(const float*)(Lb + sj[c0i + t]);
        #pragma unroll
        for (int t = 0; t < 4; t++) {
            const ulonglong2* wp = (const ulonglong2*)&w_s[(c0i + t) * 16];
            ulonglong2 w01 = wp[0];
            ulonglong2 w23 = wp[1];
            ulonglong2 w45 = wp[2];
            ulonglong2 w67 = wp[3];
            unsigned long long Lv2 = pack2(Lr[t]);
            ffma2(acc2[0], w01.x, Lv2);
            ffma2(acc2[1], w01.y, Lv2);
            ffma2(acc2[2], w23.x, Lv2);
            ffma2(acc2[3], w23.y, Lv2);
            ffma2(acc2[4], w45.x, Lv2);
            ffma2(acc2[5], w45.y, Lv2);
            ffma2(acc2[6], w67.x, Lv2);
            ffma2(acc2[7], w67.y, Lv2);
        }
    }

    // epilogue: normalize, +V, fast ELU, bf16 store — pointer-stride address
    __nv_bfloat16* op = &g_out_bf[((size_t)(b0 * NN + i)) * D_GAT + hf];
    const float*   vp = &g_V[b0 * D_GAT + hf];
    const size_t ostride = (size_t)NN * D_GAT;
    #pragma unroll
    for (int p = 0; p < 8; p++) {
        float v0, v1;
        unpack2(acc2[p], v0, v1);
        v0 = v0 * sinv[p * 2]     + vp[0];
        v1 = v1 * sinv[p * 2 + 1] + vp[D_GAT];
        v0 = v0 > 0.f ? v0 : (__expf(v0) - 1.f);
        v1 = v1 > 0.f ? v1 : (__expf(v1) - 1.f);
        op[0]       = __float2bfloat16(v0);
        op[ostride] = __float2bfloat16(v1);
        op += 2 * ostride;
        vp += 2 * D_GAT;
    }
}

// ---------------- pooling logits: logits[b][n] = out_bf[b,n,:] . pool_q -----
__global__ void logits_kernel(const float* __restrict__ pool_q)
{
    __shared__ float sq[D_GAT];
    const int tid = threadIdx.x;
    const int wid = tid >> 5, lane = tid & 31;
    #pragma unroll
    for (int k = 0; k < 8; k++) sq[tid + k * 256] = pool_q[tid + k * 256];
    __syncthreads();

    const int b = blockIdx.x >> 5;
    const int n = (blockIdx.x & 31) * 8 + wid;
    const uint2* row = (const uint2*)&g_out_bf[((size_t)(b * NN + n)) * D_GAT];
    float s = 0.f;
    #pragma unroll
    for (int k = 0; k < 16; k++) {
        int idx = lane + k * 32;
        uint2 v = row[idx];
        const __nv_bfloat162* p0 = (const __nv_bfloat162*)&v.x;
        const __nv_bfloat162* p1 = (const __nv_bfloat162*)&v.y;
        float2 f0 = __bfloat1622float2(*p0);
        float2 f1 = __bfloat1622float2(*p1);
        const float* qp = &sq[idx * 4];
        s += f0.x * qp[0] + f0.y * qp[1] + f1.x * qp[2] + f1.y * qp[3];
    }
    s = warp_sum(s);
    if (lane == 0) g_logits[b * NN + n] = s;
}

// ---------------- fused pooling softmax + pooled (2 d per thread) -----------
__global__ void pooled_pw_kernel()
{
    __shared__ float pw_s[NN];
    __shared__ float sh[8];
    __shared__ float bc;
    const int b = blockIdx.y;
    const int t = threadIdx.x;

    float x = g_logits[b * NN + t];
    float m = warp_max(x);
    if ((t & 31) == 0) sh[t >> 5] = m;
    __syncthreads();
    if (t < 8) {
        float v = sh[t];
        #pragma unroll
        for (int o = 4; o; o >>= 1) v = fmaxf(v, __shfl_xor_sync(0xffu, v, o));
        if (t == 0) bc = v;
    }
    __syncthreads();
    float M = bc;
    float e = __expf(x - M);
    float s = warp_sum(e);
    if ((t & 31) == 0) sh[t >> 5] = s;
    __syncthreads();
    if (t < 8) {
        float v = sh[t];
        #pragma unroll
        for (int o = 4; o; o >>= 1) v += __shfl_xor_sync(0xffu, v, o);
        if (t == 0) bc = v;
    }
    __syncthreads();
    pw_s[t] = e / bc;
    __syncthreads();

    // each thread handles a d-pair; bf16x2 loads, unroll 8 (MLP 8)
    const int dp = blockIdx.x * 256 + t;              // d-pair index
    const __nv_bfloat162* base =
        (const __nv_bfloat162*)&g_out_bf[(size_t)b * NN * D_GAT] + dp;
    float a0 = 0.f, a1 = 0.f;
    #pragma unroll 8
    for (int n = 0; n < NN; n++) {
        float2 v = __bfloat1622float2(base[(size_t)n * (D_GAT / 2)]);
        float w = pw_s[n];
        a0 += w * v.x;
        a1 += w * v.y;
    }
    *(float2*)&g_pooled[b * D_GAT + dp * 2] = make_float2(a0, a1);
}

// ---------------- launch ----------------------------------------------------
extern "C" void kernel_launch(void* const* d_in, const int* in_sizes, int n_in,
                              void* d_out, int out_size)
{
    const float* visual = (const float*)d_in[0];   // (64, 2048)
    const float* labels = (const float*)d_in[1];   // (256, 512)
    const float* adj    = (const float*)d_in[2];   // (256, 256)
    const float* W      = (const float*)d_in[3];   // (2560, 8, 256)
    const float* a_src  = (const float*)d_in[4];
    const float* a_dst  = (const float*)d_in[5];
    const float* pool_q = (const float*)d_in[6];
    const float* fcW    = (const float*)d_in[7];   // (2048, 512)
    const float* fcb    = (const float*)d_in[8];
    float* out = (float*)d_out;                    // (64, 512)

    float *pFcpart, *pPooled;
    cudaGetSymbolAddress((void**)&pFcpart, g_fcpart);
    cudaGetSymbolAddress((void**)&pPooled, g_pooled);

    // 1: L + V projections (V as 4 K-parts), FFMA2 inner loop
    gemm_LV_kernel<<<dim3(D_GAT / 64, 8), 256>>>(labels, visual, W);
    // 2: attention scalars + V reduction + shared CSR build
    dots_kernel<<<NN * HH + BB * HH + NN / 8, 256>>>(a_src, a_dst, adj);
    // 3: fused softmax + SpMM(FFMA2) + ELU, 6 CTAs/SM  (R14 champion)
    spmm_kernel<<<NN * HH * 4, 256>>>();
    // 4: pooling logits (DRAM pass over g_out_bf)      [profiled slot]
    logits_kernel<<<BB * NN / 8, 256>>>(pool_q);
    // 5: pooling softmax + pooled (bf16x2, MLP 8)
    pooled_pw_kernel<<<dim3(D_GAT / 512, BB), 256>>>();
    // 6-7: final fc (split-K 8)
    gemm_f32_splitk<<<dim3(D_EMB / 64, 1, 8), 256>>>(
        pPooled, D_GAT, fcW, D_EMB, pFcpart, D_EMB, 256, (size_t)BB * D_EMB);
    reduce_parts<<<(BB * D_EMB) / 256, 256>>>(
        pFcpart, out, 8, (size_t)BB * D_EMB, BB * D_EMB, fcb, D_EMB - 1);
}